// round 14
// baseline (speedup 1.0000x reference)
#include <cuda_runtime.h>
#include <cstddef>

// Problem constants
#define H      1024
#define BSZ    4
#define TLEN   1024
#define G4H    4096          // 4*H
#define NTOK   4096          // BSZ*TLEN
#define VOCAB  32000

// Fused persistent kernel config
#define NCTA_T 148           // total CTAs (1 per SM)
#define NCTA_R 128           // recurrence CTAs (barrier count)
#define TPB_F  512           // 16 warps
#define UPC    8             // hidden units per CTA per layer
#define RPC    32            // gate rows per CTA per layer
#define RPW    2             // rows per warp per layer
#define WPAD   1028          // padded row stride for Whh0 slice in smem

// Projection tiling
#define CHUNKT 128           // timesteps per chunk
#define NCHUNK (TLEN / CHUNKT)           // 8
#define NTPROJ (VOCAB / 128)             // 250 n-tiles
#define TILES_PER_CHUNK (BSZ * NTPROJ)   // 1000
#define NTILES (NCHUNK * TILES_PER_CHUNK)// 8000

// Scratch (device globals; no allocations allowed)
__device__ float g_act[(size_t)NTOK * H];
__device__ float g_pre[(size_t)NTOK * G4H];
__device__ float g_hs1[(size_t)NTOK * H];
__device__ float g_h0[2 * BSZ * H];      // layer-0 h carry, parity buffered
__device__ float g_h1[2 * BSZ * H];      // layer-1 h carry, parity buffered
__device__ int g_bar_count;              // returns to 0 every launch
__device__ int g_bar_flag;               // even # of toggles per launch -> 0
__device__ int g_progress;               // completed timesteps; reset each launch
__device__ int g_tile_ctr;               // proj tile queue; reset each launch

// ---------------------------------------------------------------------------
// Packed fp32x2 helpers (FFMA2) for the pre0 SGEMM
// ---------------------------------------------------------------------------
__device__ __forceinline__ unsigned long long pk2(float x, float y) {
    unsigned long long r;
    asm("mov.b64 %0, {%1, %2};" : "=l"(r) : "f"(x), "f"(y));
    return r;
}
__device__ __forceinline__ void ffma2(unsigned long long& d,
                                      unsigned long long a,
                                      unsigned long long b) {
    asm("fma.rn.f32x2 %0, %1, %2, %0;" : "+l"(d) : "l"(a), "l"(b));
}
__device__ __forceinline__ float2 upk2(unsigned long long v) {
    float2 f;
    asm("mov.b64 {%0, %1}, %2;" : "=f"(f.x), "=f"(f.y) : "l"(v));
    return f;
}

// flat grid barrier over the 128 rec CTAs + progress publication
__device__ __forceinline__ void grid_barrier_pub(int tid, int& sense, int prog) {
    if (tid == 0) {
        sense ^= 1;
        int prev;
        asm volatile("atom.add.acq_rel.gpu.s32 %0, [%1], 1;"
                     : "=r"(prev) : "l"(&g_bar_count) : "memory");
        if (prev == NCTA_R - 1) {
            asm volatile("st.relaxed.gpu.s32 [%0], %1;"
                         :: "l"(&g_bar_count), "r"(0) : "memory");
            asm volatile("st.release.gpu.s32 [%0], %1;"
                         :: "l"(&g_progress), "r"(prog) : "memory");
            asm volatile("st.release.gpu.s32 [%0], %1;"
                         :: "l"(&g_bar_flag), "r"(sense) : "memory");
        } else {
            int f;
            do {
                asm volatile("ld.acquire.gpu.s32 %0, [%1];"
                             : "=r"(f) : "l"(&g_bar_flag) : "memory");
            } while (f != sense);
        }
    }
    __syncthreads();
}

// ---------------------------------------------------------------------------
// Reset kernel: queue + progress start at 0 every launch (replay-deterministic)
// ---------------------------------------------------------------------------
__global__ void reset_kernel()
{
    g_progress = 0;
    g_tile_ctr = 0;
}

// ---------------------------------------------------------------------------
// Embedding gather: out[n, :] = emb[x[n], :]
// ---------------------------------------------------------------------------
__global__ void embed_kernel(const int* __restrict__ x,
                             const float* __restrict__ emb,
                             float* __restrict__ out)
{
    int n = blockIdx.x;
    int tok = __ldg(&x[n]);
    const float4* src = (const float4*)(emb + (size_t)tok * H);
    float4* dst = (float4*)(out + (size_t)n * H);
    dst[threadIdx.x] = __ldg(&src[threadIdx.x]);
}

// ---------------------------------------------------------------------------
// SGEMM (pre0 only): C[M,N] = A[M,K]*B[N,K]^T + bias1 + bias2   (R13-exact)
// ---------------------------------------------------------------------------
__global__ __launch_bounds__(256, 2)
void sgemm_abt(const float* __restrict__ A, const float* __restrict__ B,
               const float* __restrict__ bias1, const float* __restrict__ bias2,
               float* __restrict__ C, int M, int N, int K)
{
    __shared__ float As[16][132];
    __shared__ float Bs[16][132];
    const int tid = threadIdx.x;
    const int bm = blockIdx.y * 128;
    const int bn = blockIdx.x * 128;
    const int tx = tid & 15;
    const int ty = tid >> 4;
    const int lr = tid >> 2;
    const int lk = (tid & 3) << 2;

    const float* Ag = A + (size_t)(bm + lr) * K + lk;
    const float* Bg = B + (size_t)(bn + lr) * K + lk;

    unsigned long long acc2[4][8];
#pragma unroll
    for (int i = 0; i < 4; i++)
#pragma unroll
        for (int j = 0; j < 8; j++) acc2[i][j] = 0ull;

    float4 a0 = *(const float4*)(Ag);
    float4 a1 = *(const float4*)(Ag + (size_t)64 * K);
    float4 b0 = *(const float4*)(Bg);
    float4 b1 = *(const float4*)(Bg + (size_t)64 * K);

    for (int k0 = 0; k0 < K; k0 += 16) {
        __syncthreads();
        As[lk+0][lr]    = a0.x; As[lk+1][lr]    = a0.y; As[lk+2][lr]    = a0.z; As[lk+3][lr]    = a0.w;
        As[lk+0][lr+64] = a1.x; As[lk+1][lr+64] = a1.y; As[lk+2][lr+64] = a1.z; As[lk+3][lr+64] = a1.w;
        Bs[lk+0][lr]    = b0.x; Bs[lk+1][lr]    = b0.y; Bs[lk+2][lr]    = b0.z; Bs[lk+3][lr]    = b0.w;
        Bs[lk+0][lr+64] = b1.x; Bs[lk+1][lr+64] = b1.y; Bs[lk+2][lr+64] = b1.z; Bs[lk+3][lr+64] = b1.w;
        __syncthreads();
        if (k0 + 16 < K) {
            a0 = *(const float4*)(Ag + k0 + 16);
            a1 = *(const float4*)(Ag + (size_t)64 * K + k0 + 16);
            b0 = *(const float4*)(Bg + k0 + 16);
            b1 = *(const float4*)(Bg + (size_t)64 * K + k0 + 16);
        }
#pragma unroll
        for (int k = 0; k < 16; k++) {
            float4 aA = *(const float4*)&As[k][ty * 4];
            float4 aB = *(const float4*)&As[k][64 + ty * 4];
            float4 bA = *(const float4*)&Bs[k][tx * 4];
            float4 bB = *(const float4*)&Bs[k][64 + tx * 4];
            unsigned long long av2[4];
            av2[0] = pk2(aA.x, aA.y);
            av2[1] = pk2(aA.z, aA.w);
            av2[2] = pk2(aB.x, aB.y);
            av2[3] = pk2(aB.z, aB.w);
            unsigned long long bv2[8];
            bv2[0] = pk2(bA.x, bA.x);
            bv2[1] = pk2(bA.y, bA.y);
            bv2[2] = pk2(bA.z, bA.z);
            bv2[3] = pk2(bA.w, bA.w);
            bv2[4] = pk2(bB.x, bB.x);
            bv2[5] = pk2(bB.y, bB.y);
            bv2[6] = pk2(bB.z, bB.z);
            bv2[7] = pk2(bB.w, bB.w);
#pragma unroll
            for (int i = 0; i < 4; i++)
#pragma unroll
                for (int j = 0; j < 8; j++)
                    ffma2(acc2[i][j], av2[i], bv2[j]);
        }
    }

    float acc[8][8];
#pragma unroll
    for (int i2 = 0; i2 < 4; i2++)
#pragma unroll
        for (int j = 0; j < 8; j++) {
            float2 v = upk2(acc2[i2][j]);
            acc[2 * i2][j]     = v.x;
            acc[2 * i2 + 1][j] = v.y;
        }

    float bb[8];
#pragma unroll
    for (int jh = 0; jh < 2; jh++)
#pragma unroll
        for (int j = 0; j < 4; j++) {
            int n = bn + jh * 64 + tx * 4 + j;
            float v = bias1 ? __ldg(&bias1[n]) : 0.f;
            if (bias2) v += __ldg(&bias2[n]);
            bb[jh * 4 + j] = v;
        }
#pragma unroll
    for (int ih = 0; ih < 2; ih++)
#pragma unroll
        for (int i = 0; i < 4; i++) {
            int m = bm + ih * 64 + ty * 4 + i;
#pragma unroll
            for (int jh = 0; jh < 2; jh++) {
                float4 v;
                v.x = acc[ih*4+i][jh*4+0] + bb[jh*4+0];
                v.y = acc[ih*4+i][jh*4+1] + bb[jh*4+1];
                v.z = acc[ih*4+i][jh*4+2] + bb[jh*4+2];
                v.w = acc[ih*4+i][jh*4+3] + bb[jh*4+3];
                *(float4*)&C[(size_t)m * N + bn + jh * 64 + tx * 4] = v;
            }
        }
}

// ---------------------------------------------------------------------------
// 512-thread 128x128 projection tile: out[m0..+128, n0..+128] =
//   hs1[m0..,:] @ Wproj[n0..,:]^T + bproj.  A loads via __ldcg (L2-fresh).
// Uses dynamic-smem region passed in (2 x 16 x 132 floats).
// ---------------------------------------------------------------------------
__device__ void proj_tile(float* smA, float* smB,
                          const float* __restrict__ A,
                          const float* __restrict__ B,
                          const float* __restrict__ bias,
                          float* __restrict__ C,
                          int m0, int n0, int tid)
{
    const int lr = tid >> 2;          // 0..127
    const int lk = (tid & 3) << 2;    // 0,4,8,12
    const int ty = tid >> 5;          // 0..15  (8 rows each)
    const int tx = tid & 31;          // 0..31  (4 cols each)
    float (*As)[132] = (float(*)[132])smA;
    float (*Bs)[132] = (float(*)[132])smB;

    const float* Ag = A + (size_t)(m0 + lr) * H + lk;
    const float* Bg = B + (size_t)(n0 + lr) * H + lk;

    float acc[8][4];
#pragma unroll
    for (int i = 0; i < 8; i++)
#pragma unroll
        for (int j = 0; j < 4; j++) acc[i][j] = 0.f;

    float4 a0 = __ldcg((const float4*)Ag);
    float4 b0 = *(const float4*)Bg;

    for (int k0 = 0; k0 < H; k0 += 16) {
        __syncthreads();
        As[lk+0][lr] = a0.x; As[lk+1][lr] = a0.y; As[lk+2][lr] = a0.z; As[lk+3][lr] = a0.w;
        Bs[lk+0][lr] = b0.x; Bs[lk+1][lr] = b0.y; Bs[lk+2][lr] = b0.z; Bs[lk+3][lr] = b0.w;
        __syncthreads();
        if (k0 + 16 < H) {
            a0 = __ldcg((const float4*)(Ag + k0 + 16));
            b0 = *(const float4*)(Bg + k0 + 16);
        }
#pragma unroll
        for (int k = 0; k < 16; k++) {
            float4 aL = *(const float4*)&As[k][ty * 8];
            float4 aH = *(const float4*)&As[k][ty * 8 + 4];
            float4 bv = *(const float4*)&Bs[k][tx * 4];
            float av[8] = {aL.x, aL.y, aL.z, aL.w, aH.x, aH.y, aH.z, aH.w};
#pragma unroll
            for (int i = 0; i < 8; i++) {
                acc[i][0] += av[i] * bv.x;
                acc[i][1] += av[i] * bv.y;
                acc[i][2] += av[i] * bv.z;
                acc[i][3] += av[i] * bv.w;
            }
        }
    }

    float4 bb = __ldg((const float4*)&bias[n0 + tx * 4]);
#pragma unroll
    for (int i = 0; i < 8; i++) {
        int m = m0 + ty * 8 + i;
        float4 v;
        v.x = acc[i][0] + bb.x;
        v.y = acc[i][1] + bb.y;
        v.z = acc[i][2] + bb.z;
        v.w = acc[i][3] + bb.w;
        *(float4*)&C[(size_t)m * VOCAB + n0 + tx * 4] = v;
    }
}

// ---------------------------------------------------------------------------
// Fused persistent kernel: 148 CTAs (1/SM).
//   CTA < 128 : two-layer wavefront LSTM (R13-exact math), publishing
//               g_progress each superstep; afterwards joins the proj queue.
//   CTA >= 128: projection worker from launch — pulls tiles from g_tile_ctr,
//               acquire-polls g_progress for the tile's time chunk.
// ---------------------------------------------------------------------------
__global__ __launch_bounds__(TPB_F, 1)
void lstm_fused(const float* __restrict__ pre0,
                const float* __restrict__ Whh0,
                const float* __restrict__ Whh1,
                const float* __restrict__ Wih1,
                const float* __restrict__ bih1,
                const float* __restrict__ bhh1,
                float* __restrict__ hs1,
                const float* __restrict__ Wproj,
                const float* __restrict__ bproj,
                float* __restrict__ out)
{
    extern __shared__ float sm[];
    __shared__ int s_tile;
    const int tid  = threadIdx.x;
    const int cta  = blockIdx.x;

    if (cta < NCTA_R) {
        // ================= recurrence path (R13-exact) =================
        float* whh0_s = sm;                        // RPC * WPAD
        float* h0_s   = whh0_s + RPC * WPAD;       // BSZ * H
        float* h1_s   = h0_s + BSZ * H;            // BSZ * H
        float* z_s    = h1_s + BSZ * H;            // 256
        float* c_s    = z_s + 256;                 // 64

        const int warp = tid >> 5;
        const int lane = tid & 31;

        for (int i = tid; i < RPC * H; i += TPB_F) {
            int r = i >> 10;
            int k = i & (H - 1);
            int grow = (r >> 3) * H + cta * UPC + (r & 7);
            whh0_s[r * WPAD + k] = __ldg(&Whh0[(size_t)grow * H + k]);
        }
        if (tid < 64) c_s[tid] = 0.f;

        float gb0 = 0.f, gb1 = 0.f, gb2 = 0.f, gb3 = 0.f;
        int u1 = 0, b1 = 0, col1 = 0;
        if (tid >= 32 && tid < 64) {
            u1 = (tid - 32) >> 2;
            b1 = (tid - 32) & 3;
            col1 = cta * UPC + u1;
            gb0 = __ldg(&bih1[col1])         + __ldg(&bhh1[col1]);
            gb1 = __ldg(&bih1[H + col1])     + __ldg(&bhh1[H + col1]);
            gb2 = __ldg(&bih1[2 * H + col1]) + __ldg(&bhh1[2 * H + col1]);
            gb3 = __ldg(&bih1[3 * H + col1]) + __ldg(&bhh1[3 * H + col1]);
        }
        int u0 = 0, b0 = 0, col0 = 0;
        if (tid < 32) {
            u0 = tid >> 2;
            b0 = tid & 3;
            col0 = cta * UPC + u0;
        }

        const int rbase = warp * RPW;
        const float* wh1p[RPW];
        const float* wi1p[RPW];
#pragma unroll
        for (int i = 0; i < RPW; i++) {
            int r = rbase + i;
            size_t grow = (size_t)((r >> 3) * H + cta * UPC + (r & 7));
            wh1p[i] = Whh1 + grow * H;
            wi1p[i] = Wih1 + grow * H;
        }

        int sense = 0;
        __syncthreads();

        for (int s = 0; s <= TLEN; s++) {
            {
                float4* d0 = (float4*)h0_s;
                float4* d1 = (float4*)h1_s;
                if (s == 0) {
                    for (int i = tid; i < (BSZ * H) / 4; i += TPB_F) {
                        d0[i] = make_float4(0.f, 0.f, 0.f, 0.f);
                        d1[i] = make_float4(0.f, 0.f, 0.f, 0.f);
                    }
                } else {
                    const float4* s0 = (const float4*)(g_h0 + ((s - 1) & 1) * BSZ * H);
                    for (int i = tid; i < (BSZ * H) / 4; i += TPB_F)
                        d0[i] = __ldcg(s0 + i);
                    if (s == 1) {
                        for (int i = tid; i < (BSZ * H) / 4; i += TPB_F)
                            d1[i] = make_float4(0.f, 0.f, 0.f, 0.f);
                    } else {
                        const float4* s1 = (const float4*)(g_h1 + ((s - 1) & 1) * BSZ * H);
                        for (int i = tid; i < (BSZ * H) / 4; i += TPB_F)
                            d1[i] = __ldcg(s1 + i);
                    }
                }
            }
            float p0 = 0.f, p1 = 0.f, p2 = 0.f, p3 = 0.f;
            if (tid < 32 && s < TLEN) {
                size_t base = ((size_t)(b0 * TLEN + s)) * G4H + cta * UPC + u0;
                p0 = __ldg(&pre0[base]);
                p1 = __ldg(&pre0[base + H]);
                p2 = __ldg(&pre0[base + 2 * H]);
                p3 = __ldg(&pre0[base + 3 * H]);
            }
            __syncthreads();

            float a0[RPW][4], a1[RPW][4];
#pragma unroll
            for (int i = 0; i < RPW; i++)
#pragma unroll
                for (int j = 0; j < 4; j++) { a0[i][j] = 0.f; a1[i][j] = 0.f; }

#pragma unroll
            for (int p = 0; p < 8; p++) {
                int k = p * 128 + (tid & 31) * 4;
                float4 x0 = *(const float4*)&h0_s[k];
                float4 x1 = *(const float4*)&h0_s[H + k];
                float4 x2 = *(const float4*)&h0_s[2 * H + k];
                float4 x3 = *(const float4*)&h0_s[3 * H + k];
                float4 y0 = *(const float4*)&h1_s[k];
                float4 y1 = *(const float4*)&h1_s[H + k];
                float4 y2 = *(const float4*)&h1_s[2 * H + k];
                float4 y3 = *(const float4*)&h1_s[3 * H + k];
#pragma unroll
                for (int i = 0; i < RPW; i++) {
                    float4 w0 = *(const float4*)&whh0_s[(rbase + i) * WPAD + k];
                    a0[i][0] += w0.x*x0.x + w0.y*x0.y + w0.z*x0.z + w0.w*x0.w;
                    a0[i][1] += w0.x*x1.x + w0.y*x1.y + w0.z*x1.z + w0.w*x1.w;
                    a0[i][2] += w0.x*x2.x + w0.y*x2.y + w0.z*x2.z + w0.w*x2.w;
                    a0[i][3] += w0.x*x3.x + w0.y*x3.y + w0.z*x3.z + w0.w*x3.w;
                    float4 wa = __ldcg((const float4*)(wh1p[i] + k));
                    float4 wb = __ldcg((const float4*)(wi1p[i] + k));
                    a1[i][0] += wa.x*y0.x + wa.y*y0.y + wa.z*y0.z + wa.w*y0.w
                              + wb.x*x0.x + wb.y*x0.y + wb.z*x0.z + wb.w*x0.w;
                    a1[i][1] += wa.x*y1.x + wa.y*y1.y + wa.z*y1.z + wa.w*y1.w
                              + wb.x*x1.x + wb.y*x1.y + wb.z*x1.z + wb.w*x1.w;
                    a1[i][2] += wa.x*y2.x + wa.y*y2.y + wa.z*y2.z + wa.w*y2.w
                              + wb.x*x2.x + wb.y*x2.y + wb.z*x2.z + wb.w*x2.w;
                    a1[i][3] += wa.x*y3.x + wa.y*y3.y + wa.z*y3.z + wa.w*y3.w
                              + wb.x*x3.x + wb.y*x3.y + wb.z*x3.z + wb.w*x3.w;
                }
            }
#pragma unroll
            for (int i = 0; i < RPW; i++)
#pragma unroll
                for (int j = 0; j < 4; j++) {
                    float v = a0[i][j];
                    v += __shfl_xor_sync(0xffffffffu, v, 16);
                    v += __shfl_xor_sync(0xffffffffu, v, 8);
                    v += __shfl_xor_sync(0xffffffffu, v, 4);
                    v += __shfl_xor_sync(0xffffffffu, v, 2);
                    v += __shfl_xor_sync(0xffffffffu, v, 1);
                    a0[i][j] = v;
                    float w = a1[i][j];
                    w += __shfl_xor_sync(0xffffffffu, w, 16);
                    w += __shfl_xor_sync(0xffffffffu, w, 8);
                    w += __shfl_xor_sync(0xffffffffu, w, 4);
                    w += __shfl_xor_sync(0xffffffffu, w, 2);
                    w += __shfl_xor_sync(0xffffffffu, w, 1);
                    a1[i][j] = w;
                }
            if (lane == 0) {
#pragma unroll
                for (int i = 0; i < RPW; i++)
#pragma unroll
                    for (int j = 0; j < 4; j++) {
                        z_s[(rbase + i) * 4 + j]       = a0[i][j];
                        z_s[128 + (rbase + i) * 4 + j] = a1[i][j];
                    }
            }
            __syncthreads();

            if (tid < 32 && s < TLEN) {
                float zi = z_s[u0 * 4 + b0] + p0;
                float zf = z_s[(8 + u0) * 4 + b0] + p1;
                float zg = z_s[(16 + u0) * 4 + b0] + p2;
                float zo = z_s[(24 + u0) * 4 + b0] + p3;
                float ig = 1.f / (1.f + __expf(-zi));
                float fg = 1.f / (1.f + __expf(-zf));
                float gg = tanhf(zg);
                float og = 1.f / (1.f + __expf(-zo));
                float c = fg * c_s[tid] + ig * gg;
                c_s[tid] = c;
                float hval = og * tanhf(c);
                __stcg(&g_h0[(s & 1) * BSZ * H + b0 * H + col0], hval);
            }
            if (tid >= 32 && tid < 64 && s >= 1) {
                float zi = z_s[128 + u1 * 4 + b1] + gb0;
                float zf = z_s[128 + (8 + u1) * 4 + b1] + gb1;
                float zg = z_s[128 + (16 + u1) * 4 + b1] + gb2;
                float zo = z_s[128 + (24 + u1) * 4 + b1] + gb3;
                float ig = 1.f / (1.f + __expf(-zi));
                float fg = 1.f / (1.f + __expf(-zf));
                float gg = tanhf(zg);
                float og = 1.f / (1.f + __expf(-zo));
                float c = fg * c_s[tid] + ig * gg;
                c_s[tid] = c;
                float hval = og * tanhf(c);
                __stcg(&g_h1[(s & 1) * BSZ * H + b1 * H + col1], hval);
                hs1[((size_t)(b1 * TLEN + (s - 1))) * H + col1] = hval;
            }
            __syncthreads();

            grid_barrier_pub(tid, sense, s);
        }
        // extra barrier for even toggle parity across replays
        grid_barrier_pub(tid, sense, TLEN);
    }

    // ================= projection queue (all CTAs) =================
    // rec CTAs arrive here after the wavefront; workers from the start.
    float* smA = sm;
    float* smB = sm + 16 * 132;
    for (;;) {
        if (tid == 0) s_tile = atomicAdd(&g_tile_ctr, 1);
        __syncthreads();
        int tile = s_tile;
        if (tile >= NTILES) break;

        int chunk = tile / TILES_PER_CHUNK;
        int rem   = tile % TILES_PER_CHUNK;
        int nt    = rem >> 2;          // 0..249 (4 consecutive tiles share nt)
        int b     = rem & 3;
        int m0    = b * TLEN + chunk * CHUNKT;
        int n0    = nt * 128;

        // wait until hs1 timesteps [0, (chunk+1)*128) are published
        if (tid == 0) {
            int need = (chunk + 1) * CHUNKT;
            int v;
            do {
                asm volatile("ld.acquire.gpu.s32 %0, [%1];"
                             : "=r"(v) : "l"(&g_progress) : "memory");
            } while (v < need);
        }
        __syncthreads();

        proj_tile(smA, smB, hs1, Wproj, bproj, out, m0, n0, tid);
        __syncthreads();
    }
}

// ---------------------------------------------------------------------------
// Host launcher (graph-capturable: kernels only, single stream)
// ---------------------------------------------------------------------------
extern "C" void kernel_launch(void* const* d_in, const int* in_sizes, int n_in,
                              void* d_out, int out_size)
{
    (void)in_sizes; (void)n_in; (void)out_size;
    const int*   x     = (const int*)  d_in[0];
    const float* emb   = (const float*)d_in[1];
    const float* Wproj = (const float*)d_in[2];
    const float* bproj = (const float*)d_in[3];
    const float* Wih0  = (const float*)d_in[4];
    const float* Whh0  = (const float*)d_in[5];
    const float* bih0  = (const float*)d_in[6];
    const float* bhh0  = (const float*)d_in[7];
    const float* Wih1  = (const float*)d_in[8];
    const float* Whh1  = (const float*)d_in[9];
    const float* bih1  = (const float*)d_in[10];
    const float* bhh1  = (const float*)d_in[11];
    float* out = (float*)d_out;

    float *act, *pre, *hs1;
    cudaGetSymbolAddress((void**)&act, g_act);
    cudaGetSymbolAddress((void**)&pre, g_pre);
    cudaGetSymbolAddress((void**)&hs1, g_hs1);

    const int RSMEM = (RPC * WPAD + 2 * BSZ * H + 256 + 64) * 4;
    cudaFuncSetAttribute(lstm_fused,
                         cudaFuncAttributeMaxDynamicSharedMemorySize, RSMEM);

    // 0) reset queue/progress (replay-deterministic)
    reset_kernel<<<1, 1>>>();

    // 1) embedding
    embed_kernel<<<NTOK, 256>>>(x, emb, act);

    // 2) layer-0 input GEMM: pre = act @ Wih0^T + bih0 + bhh0
    dim3 g1(G4H / 128, NTOK / 128);
    sgemm_abt<<<g1, 256>>>(act, Wih0, bih0, bhh0, pre, NTOK, G4H, H);

    // 3) fused persistent kernel: wavefront recurrence + overlapped projection
    lstm_fused<<<NCTA_T, TPB_F, RSMEM>>>(pre, Whh0, Whh1, Wih1, bih1, bhh1,
                                         hs1, Wproj, bproj, out);
}

// round 15
// speedup vs baseline: 1.0452x; 1.0452x over previous
#include <cuda_runtime.h>
#include <cstddef>

// Problem constants
#define H      1024
#define BSZ    4
#define TLEN   1024
#define G4H    4096          // 4*H
#define NTOK   4096          // BSZ*TLEN
#define VOCAB  32000

// Fused persistent kernel config
#define NCTA_T 148           // total CTAs (1 per SM)
#define NCTA_R 128           // recurrence CTAs (barrier count)
#define TPB_F  512           // 16 warps
#define UPC    8             // hidden units per CTA per layer
#define RPC    32            // gate rows per CTA per layer
#define RPW    2             // rows per warp per layer
#define WPAD   1028          // padded row stride for Whh0 slice in smem

// Projection tiling: 128 (m) x 256 (n) tiles
#define CHUNKT 128           // timesteps per chunk
#define NCHUNK (TLEN / CHUNKT)           // 8
#define NTPROJ (VOCAB / 256)             // 125 n-tiles
#define TILES_PER_CHUNK (BSZ * NTPROJ)   // 500
#define NTILES (NCHUNK * TILES_PER_CHUNK)// 4000

// Scratch (device globals; no allocations allowed)
__device__ float g_act[(size_t)NTOK * H];
__device__ float g_pre[(size_t)NTOK * G4H];
__device__ float g_hs1[(size_t)NTOK * H];
__device__ float g_h0[2 * BSZ * H];      // layer-0 h carry, parity buffered
__device__ float g_h1[2 * BSZ * H];      // layer-1 h carry, parity buffered
// control words on PRIVATE 128B lines (R14 shared a line -> barrier contention)
__device__ __align__(128) int g_bar_count;   // self-resets every launch
__device__ __align__(128) int g_bar_flag;    // even # toggles -> returns to 0
__device__ __align__(128) int g_progress;    // reset each launch
__device__ __align__(128) int g_tile_ctr;    // reset each launch

// ---------------------------------------------------------------------------
// Packed fp32x2 helpers (FFMA2)
// ---------------------------------------------------------------------------
__device__ __forceinline__ unsigned long long pk2(float x, float y) {
    unsigned long long r;
    asm("mov.b64 %0, {%1, %2};" : "=l"(r) : "f"(x), "f"(y));
    return r;
}
__device__ __forceinline__ void ffma2(unsigned long long& d,
                                      unsigned long long a,
                                      unsigned long long b) {
    asm("fma.rn.f32x2 %0, %1, %2, %0;" : "+l"(d) : "l"(a), "l"(b));
}
__device__ __forceinline__ float2 upk2(unsigned long long v) {
    float2 f;
    asm("mov.b64 {%0, %1}, %2;" : "=f"(f.x), "=f"(f.y) : "l"(v));
    return f;
}

// flat grid barrier over the 128 rec CTAs + progress publication
__device__ __forceinline__ void grid_barrier_pub(int tid, int& sense, int prog) {
    if (tid == 0) {
        sense ^= 1;
        int prev;
        asm volatile("atom.add.acq_rel.gpu.s32 %0, [%1], 1;"
                     : "=r"(prev) : "l"(&g_bar_count) : "memory");
        if (prev == NCTA_R - 1) {
            asm volatile("st.relaxed.gpu.s32 [%0], %1;"
                         :: "l"(&g_bar_count), "r"(0) : "memory");
            asm volatile("st.release.gpu.s32 [%0], %1;"
                         :: "l"(&g_progress), "r"(prog) : "memory");
            asm volatile("st.release.gpu.s32 [%0], %1;"
                         :: "l"(&g_bar_flag), "r"(sense) : "memory");
        } else {
            int f;
            do {
                asm volatile("ld.acquire.gpu.s32 %0, [%1];"
                             : "=r"(f) : "l"(&g_bar_flag) : "memory");
            } while (f != sense);
        }
    }
    __syncthreads();
}

// ---------------------------------------------------------------------------
// Reset kernel (replay-deterministic queue/progress)
// ---------------------------------------------------------------------------
__global__ void reset_kernel()
{
    g_progress = 0;
    g_tile_ctr = 0;
}

// ---------------------------------------------------------------------------
// Embedding gather
// ---------------------------------------------------------------------------
__global__ void embed_kernel(const int* __restrict__ x,
                             const float* __restrict__ emb,
                             float* __restrict__ out)
{
    int n = blockIdx.x;
    int tok = __ldg(&x[n]);
    const float4* src = (const float4*)(emb + (size_t)tok * H);
    float4* dst = (float4*)(out + (size_t)n * H);
    dst[threadIdx.x] = __ldg(&src[threadIdx.x]);
}

// ---------------------------------------------------------------------------
// SGEMM (pre0 only): C[M,N] = A[M,K]*B[N,K]^T + bias1 + bias2   (R13-exact)
// ---------------------------------------------------------------------------
__global__ __launch_bounds__(256, 2)
void sgemm_abt(const float* __restrict__ A, const float* __restrict__ B,
               const float* __restrict__ bias1, const float* __restrict__ bias2,
               float* __restrict__ C, int M, int N, int K)
{
    __shared__ float As[16][132];
    __shared__ float Bs[16][132];
    const int tid = threadIdx.x;
    const int bm = blockIdx.y * 128;
    const int bn = blockIdx.x * 128;
    const int tx = tid & 15;
    const int ty = tid >> 4;
    const int lr = tid >> 2;
    const int lk = (tid & 3) << 2;

    const float* Ag = A + (size_t)(bm + lr) * K + lk;
    const float* Bg = B + (size_t)(bn + lr) * K + lk;

    unsigned long long acc2[4][8];
#pragma unroll
    for (int i = 0; i < 4; i++)
#pragma unroll
        for (int j = 0; j < 8; j++) acc2[i][j] = 0ull;

    float4 a0 = *(const float4*)(Ag);
    float4 a1 = *(const float4*)(Ag + (size_t)64 * K);
    float4 b0 = *(const float4*)(Bg);
    float4 b1 = *(const float4*)(Bg + (size_t)64 * K);

    for (int k0 = 0; k0 < K; k0 += 16) {
        __syncthreads();
        As[lk+0][lr]    = a0.x; As[lk+1][lr]    = a0.y; As[lk+2][lr]    = a0.z; As[lk+3][lr]    = a0.w;
        As[lk+0][lr+64] = a1.x; As[lk+1][lr+64] = a1.y; As[lk+2][lr+64] = a1.z; As[lk+3][lr+64] = a1.w;
        Bs[lk+0][lr]    = b0.x; Bs[lk+1][lr]    = b0.y; Bs[lk+2][lr]    = b0.z; Bs[lk+3][lr]    = b0.w;
        Bs[lk+0][lr+64] = b1.x; Bs[lk+1][lr+64] = b1.y; Bs[lk+2][lr+64] = b1.z; Bs[lk+3][lr+64] = b1.w;
        __syncthreads();
        if (k0 + 16 < K) {
            a0 = *(const float4*)(Ag + k0 + 16);
            a1 = *(const float4*)(Ag + (size_t)64 * K + k0 + 16);
            b0 = *(const float4*)(Bg + k0 + 16);
            b1 = *(const float4*)(Bg + (size_t)64 * K + k0 + 16);
        }
#pragma unroll
        for (int k = 0; k < 16; k++) {
            float4 aA = *(const float4*)&As[k][ty * 4];
            float4 aB = *(const float4*)&As[k][64 + ty * 4];
            float4 bA = *(const float4*)&Bs[k][tx * 4];
            float4 bB = *(const float4*)&Bs[k][64 + tx * 4];
            unsigned long long av2[4];
            av2[0] = pk2(aA.x, aA.y);
            av2[1] = pk2(aA.z, aA.w);
            av2[2] = pk2(aB.x, aB.y);
            av2[3] = pk2(aB.z, aB.w);
            unsigned long long bv2[8];
            bv2[0] = pk2(bA.x, bA.x);
            bv2[1] = pk2(bA.y, bA.y);
            bv2[2] = pk2(bA.z, bA.z);
            bv2[3] = pk2(bA.w, bA.w);
            bv2[4] = pk2(bB.x, bB.x);
            bv2[5] = pk2(bB.y, bB.y);
            bv2[6] = pk2(bB.z, bB.z);
            bv2[7] = pk2(bB.w, bB.w);
#pragma unroll
            for (int i = 0; i < 4; i++)
#pragma unroll
                for (int j = 0; j < 8; j++)
                    ffma2(acc2[i][j], av2[i], bv2[j]);
        }
    }

    float acc[8][8];
#pragma unroll
    for (int i2 = 0; i2 < 4; i2++)
#pragma unroll
        for (int j = 0; j < 8; j++) {
            float2 v = upk2(acc2[i2][j]);
            acc[2 * i2][j]     = v.x;
            acc[2 * i2 + 1][j] = v.y;
        }

    float bb[8];
#pragma unroll
    for (int jh = 0; jh < 2; jh++)
#pragma unroll
        for (int j = 0; j < 4; j++) {
            int n = bn + jh * 64 + tx * 4 + j;
            float v = bias1 ? __ldg(&bias1[n]) : 0.f;
            if (bias2) v += __ldg(&bias2[n]);
            bb[jh * 4 + j] = v;
        }
#pragma unroll
    for (int ih = 0; ih < 2; ih++)
#pragma unroll
        for (int i = 0; i < 4; i++) {
            int m = bm + ih * 64 + ty * 4 + i;
#pragma unroll
            for (int jh = 0; jh < 2; jh++) {
                float4 v;
                v.x = acc[ih*4+i][jh*4+0] + bb[jh*4+0];
                v.y = acc[ih*4+i][jh*4+1] + bb[jh*4+1];
                v.z = acc[ih*4+i][jh*4+2] + bb[jh*4+2];
                v.w = acc[ih*4+i][jh*4+3] + bb[jh*4+3];
                *(float4*)&C[(size_t)m * N + bn + jh * 64 + tx * 4] = v;
            }
        }
}

// ---------------------------------------------------------------------------
// 512-thread 128x256 projection tile with FFMA2 (same per-FLOP rate as
// sgemm_abt; ascending-k chains -> logits bitwise-identical to R13).
//   out[m0..+128, n0..+256] = hs1[m0..,:] @ Wproj[n0..,:]^T + bproj
// smem: As[16][132] + Bs[16][264]
// ---------------------------------------------------------------------------
__device__ void proj_tile(float* smA, float* smB,
                          const float* __restrict__ A,
                          const float* __restrict__ B,
                          const float* __restrict__ bias,
                          float* __restrict__ C,
                          int m0, int n0, int tid)
{
    const int lr = tid >> 2;          // 0..127
    const int lk = (tid & 3) << 2;    // 0,4,8,12
    const int ty = tid >> 5;          // 0..15 -> rows ty*8..+7
    const int tx = tid & 31;          // cols tx*4 and 128+tx*4
    float (*As)[132] = (float(*)[132])smA;
    float (*Bs)[264] = (float(*)[264])smB;

    const float* Ag  = A + (size_t)(m0 + lr) * H + lk;
    const float* Bg0 = B + (size_t)(n0 + lr) * H + lk;
    const float* Bg1 = B + (size_t)(n0 + 128 + lr) * H + lk;

    unsigned long long acc2[4][8];
#pragma unroll
    for (int i = 0; i < 4; i++)
#pragma unroll
        for (int j = 0; j < 8; j++) acc2[i][j] = 0ull;

    float4 a0 = __ldcg((const float4*)Ag);
    float4 b0 = __ldg((const float4*)Bg0);
    float4 b1 = __ldg((const float4*)Bg1);

    for (int k0 = 0; k0 < H; k0 += 16) {
        __syncthreads();
        As[lk+0][lr]     = a0.x; As[lk+1][lr]     = a0.y; As[lk+2][lr]     = a0.z; As[lk+3][lr]     = a0.w;
        Bs[lk+0][lr]     = b0.x; Bs[lk+1][lr]     = b0.y; Bs[lk+2][lr]     = b0.z; Bs[lk+3][lr]     = b0.w;
        Bs[lk+0][lr+128] = b1.x; Bs[lk+1][lr+128] = b1.y; Bs[lk+2][lr+128] = b1.z; Bs[lk+3][lr+128] = b1.w;
        __syncthreads();
        if (k0 + 16 < H) {
            a0 = __ldcg((const float4*)(Ag + k0 + 16));
            b0 = __ldg((const float4*)(Bg0 + k0 + 16));
            b1 = __ldg((const float4*)(Bg1 + k0 + 16));
        }
#pragma unroll
        for (int k = 0; k < 16; k++) {
            float4 aL = *(const float4*)&As[k][ty * 8];
            float4 aH = *(const float4*)&As[k][ty * 8 + 4];
            float4 bA = *(const float4*)&Bs[k][tx * 4];
            float4 bB = *(const float4*)&Bs[k][128 + tx * 4];
            unsigned long long av2[4];
            av2[0] = pk2(aL.x, aL.y);
            av2[1] = pk2(aL.z, aL.w);
            av2[2] = pk2(aH.x, aH.y);
            av2[3] = pk2(aH.z, aH.w);
            unsigned long long bv2[8];
            bv2[0] = pk2(bA.x, bA.x);
            bv2[1] = pk2(bA.y, bA.y);
            bv2[2] = pk2(bA.z, bA.z);
            bv2[3] = pk2(bA.w, bA.w);
            bv2[4] = pk2(bB.x, bB.x);
            bv2[5] = pk2(bB.y, bB.y);
            bv2[6] = pk2(bB.z, bB.z);
            bv2[7] = pk2(bB.w, bB.w);
#pragma unroll
            for (int i = 0; i < 4; i++)
#pragma unroll
                for (int j = 0; j < 8; j++)
                    ffma2(acc2[i][j], av2[i], bv2[j]);
        }
    }

    float4 bbA = __ldg((const float4*)&bias[n0 + tx * 4]);
    float4 bbB = __ldg((const float4*)&bias[n0 + 128 + tx * 4]);
    float bb[8] = {bbA.x, bbA.y, bbA.z, bbA.w, bbB.x, bbB.y, bbB.z, bbB.w};

#pragma unroll
    for (int i2 = 0; i2 < 4; i2++) {
        float accLo[8], accHi[8];
#pragma unroll
        for (int j = 0; j < 8; j++) {
            float2 v = upk2(acc2[i2][j]);
            accLo[j] = v.x + bb[j];
            accHi[j] = v.y + bb[j];
        }
        int r0 = m0 + ty * 8 + 2 * i2;
#pragma unroll
        for (int jh = 0; jh < 2; jh++) {
            int col = n0 + jh * 128 + tx * 4;
            float4 vLo = make_float4(accLo[jh*4+0], accLo[jh*4+1], accLo[jh*4+2], accLo[jh*4+3]);
            float4 vHi = make_float4(accHi[jh*4+0], accHi[jh*4+1], accHi[jh*4+2], accHi[jh*4+3]);
            *(float4*)&C[(size_t)r0 * VOCAB + col]       = vLo;
            *(float4*)&C[(size_t)(r0 + 1) * VOCAB + col] = vHi;
        }
    }
}

// ---------------------------------------------------------------------------
// Fused persistent kernel: 148 CTAs (1/SM).
//   CTA < 128 : two-layer wavefront LSTM (R13-exact math), publishes
//               g_progress each superstep; afterwards joins the proj queue.
//   CTA >= 128: projection worker from launch.
// ---------------------------------------------------------------------------
__global__ __launch_bounds__(TPB_F, 1)
void lstm_fused(const float* __restrict__ pre0,
                const float* __restrict__ Whh0,
                const float* __restrict__ Whh1,
                const float* __restrict__ Wih1,
                const float* __restrict__ bih1,
                const float* __restrict__ bhh1,
                float* __restrict__ hs1,
                const float* __restrict__ Wproj,
                const float* __restrict__ bproj,
                float* __restrict__ out)
{
    extern __shared__ float sm[];
    __shared__ int s_tile;
    const int tid  = threadIdx.x;
    const int cta  = blockIdx.x;

    if (cta < NCTA_R) {
        // ================= recurrence path (R13-exact) =================
        float* whh0_s = sm;                        // RPC * WPAD
        float* h0_s   = whh0_s + RPC * WPAD;       // BSZ * H
        float* h1_s   = h0_s + BSZ * H;            // BSZ * H
        float* z_s    = h1_s + BSZ * H;            // 256
        float* c_s    = z_s + 256;                 // 64

        const int warp = tid >> 5;
        const int lane = tid & 31;

        for (int i = tid; i < RPC * H; i += TPB_F) {
            int r = i >> 10;
            int k = i & (H - 1);
            int grow = (r >> 3) * H + cta * UPC + (r & 7);
            whh0_s[r * WPAD + k] = __ldg(&Whh0[(size_t)grow * H + k]);
        }
        if (tid < 64) c_s[tid] = 0.f;

        float gb0 = 0.f, gb1 = 0.f, gb2 = 0.f, gb3 = 0.f;
        int u1 = 0, b1 = 0, col1 = 0;
        if (tid >= 32 && tid < 64) {
            u1 = (tid - 32) >> 2;
            b1 = (tid - 32) & 3;
            col1 = cta * UPC + u1;
            gb0 = __ldg(&bih1[col1])         + __ldg(&bhh1[col1]);
            gb1 = __ldg(&bih1[H + col1])     + __ldg(&bhh1[H + col1]);
            gb2 = __ldg(&bih1[2 * H + col1]) + __ldg(&bhh1[2 * H + col1]);
            gb3 = __ldg(&bih1[3 * H + col1]) + __ldg(&bhh1[3 * H + col1]);
        }
        int u0 = 0, b0 = 0, col0 = 0;
        if (tid < 32) {
            u0 = tid >> 2;
            b0 = tid & 3;
            col0 = cta * UPC + u0;
        }

        const int rbase = warp * RPW;
        const float* wh1p[RPW];
        const float* wi1p[RPW];
#pragma unroll
        for (int i = 0; i < RPW; i++) {
            int r = rbase + i;
            size_t grow = (size_t)((r >> 3) * H + cta * UPC + (r & 7));
            wh1p[i] = Whh1 + grow * H;
            wi1p[i] = Wih1 + grow * H;
        }

        int sense = 0;
        __syncthreads();

        for (int s = 0; s <= TLEN; s++) {
            {
                float4* d0 = (float4*)h0_s;
                float4* d1 = (float4*)h1_s;
                if (s == 0) {
                    for (int i = tid; i < (BSZ * H) / 4; i += TPB_F) {
                        d0[i] = make_float4(0.f, 0.f, 0.f, 0.f);
                        d1[i] = make_float4(0.f, 0.f, 0.f, 0.f);
                    }
                } else {
                    const float4* s0 = (const float4*)(g_h0 + ((s - 1) & 1) * BSZ * H);
                    for (int i = tid; i < (BSZ * H) / 4; i += TPB_F)
                        d0[i] = __ldcg(s0 + i);
                    if (s == 1) {
                        for (int i = tid; i < (BSZ * H) / 4; i += TPB_F)
                            d1[i] = make_float4(0.f, 0.f, 0.f, 0.f);
                    } else {
                        const float4* s1 = (const float4*)(g_h1 + ((s - 1) & 1) * BSZ * H);
                        for (int i = tid; i < (BSZ * H) / 4; i += TPB_F)
                            d1[i] = __ldcg(s1 + i);
                    }
                }
            }
            float p0 = 0.f, p1 = 0.f, p2 = 0.f, p3 = 0.f;
            if (tid < 32 && s < TLEN) {
                size_t base = ((size_t)(b0 * TLEN + s)) * G4H + cta * UPC + u0;
                p0 = __ldg(&pre0[base]);
                p1 = __ldg(&pre0[base + H]);
                p2 = __ldg(&pre0[base + 2 * H]);
                p3 = __ldg(&pre0[base + 3 * H]);
            }
            __syncthreads();

            float a0[RPW][4], a1[RPW][4];
#pragma unroll
            for (int i = 0; i < RPW; i++)
#pragma unroll
                for (int j = 0; j < 4; j++) { a0[i][j] = 0.f; a1[i][j] = 0.f; }

#pragma unroll
            for (int p = 0; p < 8; p++) {
                int k = p * 128 + lane * 4;
                float4 x0 = *(const float4*)&h0_s[k];
                float4 x1 = *(const float4*)&h0_s[H + k];
                float4 x2 = *(const float4*)&h0_s[2 * H + k];
                float4 x3 = *(const float4*)&h0_s[3 * H + k];
                float4 y0 = *(const float4*)&h1_s[k];
                float4 y1 = *(const float4*)&h1_s[H + k];
                float4 y2 = *(const float4*)&h1_s[2 * H + k];
                float4 y3 = *(const float4*)&h1_s[3 * H + k];
#pragma unroll
                for (int i = 0; i < RPW; i++) {
                    float4 w0 = *(const float4*)&whh0_s[(rbase + i) * WPAD + k];
                    a0[i][0] += w0.x*x0.x + w0.y*x0.y + w0.z*x0.z + w0.w*x0.w;
                    a0[i][1] += w0.x*x1.x + w0.y*x1.y + w0.z*x1.z + w0.w*x1.w;
                    a0[i][2] += w0.x*x2.x + w0.y*x2.y + w0.z*x2.z + w0.w*x2.w;
                    a0[i][3] += w0.x*x3.x + w0.y*x3.y + w0.z*x3.z + w0.w*x3.w;
                    float4 wa = __ldcg((const float4*)(wh1p[i] + k));
                    float4 wb = __ldcg((const float4*)(wi1p[i] + k));
                    a1[i][0] += wa.x*y0.x + wa.y*y0.y + wa.z*y0.z + wa.w*y0.w
                              + wb.x*x0.x + wb.y*x0.y + wb.z*x0.z + wb.w*x0.w;
                    a1[i][1] += wa.x*y1.x + wa.y*y1.y + wa.z*y1.z + wa.w*y1.w
                              + wb.x*x1.x + wb.y*x1.y + wb.z*x1.z + wb.w*x1.w;
                    a1[i][2] += wa.x*y2.x + wa.y*y2.y + wa.z*y2.z + wa.w*y2.w
                              + wb.x*x2.x + wb.y*x2.y + wb.z*x2.z + wb.w*x2.w;
                    a1[i][3] += wa.x*y3.x + wa.y*y3.y + wa.z*y3.z + wa.w*y3.w
                              + wb.x*x3.x + wb.y*x3.y + wb.z*x3.z + wb.w*x3.w;
                }
            }
#pragma unroll
            for (int i = 0; i < RPW; i++)
#pragma unroll
                for (int j = 0; j < 4; j++) {
                    float v = a0[i][j];
                    v += __shfl_xor_sync(0xffffffffu, v, 16);
                    v += __shfl_xor_sync(0xffffffffu, v, 8);
                    v += __shfl_xor_sync(0xffffffffu, v, 4);
                    v += __shfl_xor_sync(0xffffffffu, v, 2);
                    v += __shfl_xor_sync(0xffffffffu, v, 1);
                    a0[i][j] = v;
                    float w = a1[i][j];
                    w += __shfl_xor_sync(0xffffffffu, w, 16);
                    w += __shfl_xor_sync(0xffffffffu, w, 8);
                    w += __shfl_xor_sync(0xffffffffu, w, 4);
                    w += __shfl_xor_sync(0xffffffffu, w, 2);
                    w += __shfl_xor_sync(0xffffffffu, w, 1);
                    a1[i][j] = w;
                }
            if (lane == 0) {
#pragma unroll
                for (int i = 0; i < RPW; i++)
#pragma unroll
                    for (int j = 0; j < 4; j++) {
                        z_s[(rbase + i) * 4 + j]       = a0[i][j];
                        z_s[128 + (rbase + i) * 4 + j] = a1[i][j];
                    }
            }
            __syncthreads();

            if (tid < 32 && s < TLEN) {
                float zi = z_s[u0 * 4 + b0] + p0;
                float zf = z_s[(8 + u0) * 4 + b0] + p1;
                float zg = z_s[(16 + u0) * 4 + b0] + p2;
                float zo = z_s[(24 + u0) * 4 + b0] + p3;
                float ig = 1.f / (1.f + __expf(-zi));
                float fg = 1.f / (1.f + __expf(-zf));
                float gg = tanhf(zg);
                float og = 1.f / (1.f + __expf(-zo));
                float c = fg * c_s[tid] + ig * gg;
                c_s[tid] = c;
                float hval = og * tanhf(c);
                __stcg(&g_h0[(s & 1) * BSZ * H + b0 * H + col0], hval);
            }
            if (tid >= 32 && tid < 64 && s >= 1) {
                float zi = z_s[128 + u1 * 4 + b1] + gb0;
                float zf = z_s[128 + (8 + u1) * 4 + b1] + gb1;
                float zg = z_s[128 + (16 + u1) * 4 + b1] + gb2;
                float zo = z_s[128 + (24 + u1) * 4 + b1] + gb3;
                float ig = 1.f / (1.f + __expf(-zi));
                float fg = 1.f / (1.f + __expf(-zf));
                float gg = tanhf(zg);
                float og = 1.f / (1.f + __expf(-zo));
                float c = fg * c_s[tid] + ig * gg;
                c_s[tid] = c;
                float hval = og * tanhf(c);
                __stcg(&g_h1[(s & 1) * BSZ * H + b1 * H + col1], hval);
                hs1[((size_t)(b1 * TLEN + (s - 1))) * H + col1] = hval;
            }
            __syncthreads();

            grid_barrier_pub(tid, sense, s);
        }
        grid_barrier_pub(tid, sense, TLEN);   // even toggle parity
    }

    // ================= projection queue (all CTAs) =================
    float* smA = sm;
    float* smB = sm + 16 * 132;
    for (;;) {
        if (tid == 0) s_tile = atomicAdd(&g_tile_ctr, 1);
        __syncthreads();
        int tile = s_tile;
        if (tile >= NTILES) break;

        int chunk = tile / TILES_PER_CHUNK;
        int rem   = tile % TILES_PER_CHUNK;
        int nt    = rem >> 2;          // 0..124 (4 consecutive tiles share nt)
        int b     = rem & 3;
        int m0    = b * TLEN + chunk * CHUNKT;
        int n0    = nt * 256;

        if (tid == 0) {
            int need = (chunk + 1) * CHUNKT;
            int v;
            for (;;) {
                asm volatile("ld.acquire.gpu.s32 %0, [%1];"
                             : "=r"(v) : "l"(&g_progress) : "memory");
                if (v >= need) break;
                __nanosleep(256);
            }
        }
        __syncthreads();

        proj_tile(smA, smB, hs1, Wproj, bproj, out, m0, n0, tid);
        __syncthreads();
    }
}

// ---------------------------------------------------------------------------
// Host launcher (graph-capturable: kernels only, single stream)
// ---------------------------------------------------------------------------
extern "C" void kernel_launch(void* const* d_in, const int* in_sizes, int n_in,
                              void* d_out, int out_size)
{
    (void)in_sizes; (void)n_in; (void)out_size;
    const int*   x     = (const int*)  d_in[0];
    const float* emb   = (const float*)d_in[1];
    const float* Wproj = (const float*)d_in[2];
    const float* bproj = (const float*)d_in[3];
    const float* Wih0  = (const float*)d_in[4];
    const float* Whh0  = (const float*)d_in[5];
    const float* bih0  = (const float*)d_in[6];
    const float* bhh0  = (const float*)d_in[7];
    const float* Wih1  = (const float*)d_in[8];
    const float* Whh1  = (const float*)d_in[9];
    const float* bih1  = (const float*)d_in[10];
    const float* bhh1  = (const float*)d_in[11];
    float* out = (float*)d_out;

    float *act, *pre, *hs1;
    cudaGetSymbolAddress((void**)&act, g_act);
    cudaGetSymbolAddress((void**)&pre, g_pre);
    cudaGetSymbolAddress((void**)&hs1, g_hs1);

    const int RSMEM = (RPC * WPAD + 2 * BSZ * H + 256 + 64) * 4;
    cudaFuncSetAttribute(lstm_fused,
                         cudaFuncAttributeMaxDynamicSharedMemorySize, RSMEM);

    // 0) reset queue/progress (replay-deterministic)
    reset_kernel<<<1, 1>>>();

    // 1) embedding
    embed_kernel<<<NTOK, 256>>>(x, emb, act);

    // 2) layer-0 input GEMM: pre = act @ Wih0^T + bih0 + bhh0
    dim3 g1(G4H / 128, NTOK / 128);
    sgemm_abt<<<g1, 256>>>(act, Wih0, bih0, bhh0, pre, NTOK, G4H, H);

    // 3) fused persistent kernel: wavefront recurrence + overlapped projection
    lstm_fused<<<NCTA_T, TPB_F, RSMEM>>>(pre, Whh0, Whh1, Wih1, bih1, bhh1,
                                         hs1, Wproj, bproj, out);
}